// round 5
// baseline (speedup 1.0000x reference)
#include <cuda_runtime.h>
#include <cuda_bf16.h>

// Problem constants
#define N 4096
#define D 512
#define NC 100          // real classes
#define NCP 128         // padded classes
#define ROWS_B 32       // rows per GEMM block
#define KT 32           // k-tile
#define NBLK (N / ROWS_B)   // 128 compute blocks
#define NT 16               // number of k-tiles = D/KT

typedef unsigned long long ull;

// Packed fp32x2 FMA (Blackwell)
#define FMA2(d, a, b) \
    asm("fma.rn.f32x2 %0, %1, %2, %3;" : "=l"(d) : "l"(a), "l"(b), "l"(d))
#define SPLAT2(d, f) \
    asm("mov.b64 %0, {%1, %1};" : "=l"(d) : "f"(f))

// Scratch (device globals; no allocation anywhere)
__device__ float  g_rscale[N];                    // per-row 1/||txt_i||
__device__ __align__(16) float g_G[NC * D];       // class sums of img_n, [c][d]
__device__ int    g_cnt[NCP];                     // class counts
__device__ double g_neg;                          // neg_similarity accumulator
__device__ double g_sumd;                         // sum_i d_i
__device__ double g_sumexpd;                      // sum_i exp(d_i)
__device__ unsigned int g_fin;                    // epilogue ticket

// ---------------------------------------------------------------------------
// Kernel 0: zero scratch accumulators (runs every replay)
// ---------------------------------------------------------------------------
__global__ void zero_kernel() {
    int idx = blockIdx.x * blockDim.x + threadIdx.x;
    if (idx < NC * D) g_G[idx] = 0.0f;
    if (idx < NCP)    g_cnt[idx] = 0;
    if (idx == 0) { g_neg = 0.0; g_sumd = 0.0; g_sumexpd = 0.0; g_fin = 0u; }
}

// ---------------------------------------------------------------------------
// Kernel 1: per-row: norms, d_i, scatter img_n into G, counts, scalar sums.
// grid = N blocks, 128 threads (thread owns 4 consecutive dims, float4)
// ---------------------------------------------------------------------------
__global__ void __launch_bounds__(128) rownorm_kernel(
    const float* __restrict__ img,
    const float* __restrict__ txt,
    const int* __restrict__ labels)
{
    const int i    = blockIdx.x;
    const int tid  = threadIdx.x;
    const int lane = tid & 31;
    const int warp = tid >> 5;

    const float4 a = reinterpret_cast<const float4*>(img + (size_t)i * D)[tid];
    const float4 b = reinterpret_cast<const float4*>(txt + (size_t)i * D)[tid];

    float sii = a.x*a.x + a.y*a.y + a.z*a.z + a.w*a.w;
    float stt = b.x*b.x + b.y*b.y + b.z*b.z + b.w*b.w;
    float sit = a.x*b.x + a.y*b.y + a.z*b.z + a.w*b.w;

    #pragma unroll
    for (int off = 16; off > 0; off >>= 1) {
        sii += __shfl_xor_sync(0xffffffffu, sii, off);
        stt += __shfl_xor_sync(0xffffffffu, stt, off);
        sit += __shfl_xor_sync(0xffffffffu, sit, off);
    }
    __shared__ float red[3][4];
    if (lane == 0) { red[0][warp] = sii; red[1][warp] = stt; red[2][warp] = sit; }
    __syncthreads();
    sii = red[0][0] + red[0][1] + red[0][2] + red[0][3];
    stt = red[1][0] + red[1][1] + red[1][2] + red[1][3];
    sit = red[2][0] + red[2][1] + red[2][2] + red[2][3];

    const float rimg = rsqrtf(sii);
    const float rtxt = rsqrtf(stt);
    int c = labels[i];
    c = min(max(c, 0), NC - 1);

    // scatter normalized image row into class sum G[c][:] (coalesced REDG)
    float* gc = g_G + (size_t)c * D + tid * 4;
    atomicAdd(gc + 0, a.x * rimg);
    atomicAdd(gc + 1, a.y * rimg);
    atomicAdd(gc + 2, a.z * rimg);
    atomicAdd(gc + 3, a.w * rimg);

    if (tid == 0) {
        g_rscale[i] = rtxt;
        const float d = sit * rimg * rtxt;
        atomicAdd(&g_cnt[c], 1);
        atomicAdd(&g_sumd, (double)d);
        atomicAdd(&g_sumexpd, (double)expf(d));
    }
}

// ---------------------------------------------------------------------------
// Kernel 2: C = txt_n @ G^T fused with neg reduction; last block writes loss.
// grid = 128 blocks, 512 threads (16 warps).
// Warp w owns rows 2w,2w+1; lane L owns class pairs (2L,2L+1),(2L+64,2L+65).
// Double-buffered smem, 1 barrier per k-tile, packed f32x2 FMA.
// ---------------------------------------------------------------------------
__global__ void __launch_bounds__(512) gemm_neg_kernel(
    const float* __restrict__ txt,
    float* __restrict__ out)
{
    __shared__ float As[2][ROWS_B][KT + 1];    // [buf][row][k]
    __shared__ float Bs[2][KT][NCP + 2];       // [buf][k][class], stride 130
    __shared__ float rs[ROWS_B];
    __shared__ double bneg[16];

    const int tid  = threadIdx.x;
    const int lane = tid & 31;
    const int warp = tid >> 5;                 // 0..15
    const int row0 = blockIdx.x * ROWS_B;

    if (tid < ROWS_B) rs[tid] = g_rscale[row0 + tid];

    // class counts for this lane's 4 classes (padded -> 0)
    const float n0 = (float)g_cnt[2*lane];
    const float n1 = (float)g_cnt[2*lane + 1];
    const float n2 = (float)g_cnt[2*lane + 64];
    const float n3 = (float)g_cnt[2*lane + 65];

    ull acc[2][2] = {};

    // staging addressing (constant per thread)
    const int ar  = tid >> 4;            // A row 0..31
    const int ak2 = (tid & 15) * 2;      // A k offset (2 floats)
    const float4 zero4 = make_float4(0.f, 0.f, 0.f, 0.f);

    float2 aReg;
    float4 bReg[2];

    // prefetch tile 0
    aReg = *reinterpret_cast<const float2*>(&txt[(size_t)(row0 + ar) * D + ak2]);
    #pragma unroll
    for (int e = 0; e < 2; e++) {
        int idx = tid + e * 512;
        int c = idx >> 3, k4 = (idx & 7) * 4;
        bReg[e] = (c < NC)
            ? *reinterpret_cast<const float4*>(&g_G[(size_t)c * D + k4])
            : zero4;
    }
    __syncthreads();   // rs visible
    const float ascale = rs[ar];

    // stage tile 0 into buffer 0
    As[0][ar][ak2 + 0] = aReg.x * ascale;
    As[0][ar][ak2 + 1] = aReg.y * ascale;
    #pragma unroll
    for (int e = 0; e < 2; e++) {
        int idx = tid + e * 512;
        int c = idx >> 3, k4 = (idx & 7) * 4;
        Bs[0][k4 + 0][c] = bReg[e].x;
        Bs[0][k4 + 1][c] = bReg[e].y;
        Bs[0][k4 + 2][c] = bReg[e].z;
        Bs[0][k4 + 3][c] = bReg[e].w;
    }

    #pragma unroll 1
    for (int t = 0; t < NT; t++) {
        const int p = t & 1;

        // issue global prefetch for tile t+1 (overlaps barrier + compute)
        if (t < NT - 1) {
            const int k0 = (t + 1) * KT;
            aReg = *reinterpret_cast<const float2*>(&txt[(size_t)(row0 + ar) * D + k0 + ak2]);
            #pragma unroll
            for (int e = 0; e < 2; e++) {
                int idx = tid + e * 512;
                int c = idx >> 3, k4 = (idx & 7) * 4;
                bReg[e] = (c < NC)
                    ? *reinterpret_cast<const float4*>(&g_G[(size_t)c * D + k0 + k4])
                    : zero4;
            }
        }

        __syncthreads();   // buffer p fully staged

        // compute on buffer p
        #pragma unroll
        for (int kk = 0; kk < KT; kk++) {
            const float a0 = As[p][2 * warp][kk];
            const float a1 = As[p][2 * warp + 1][kk];
            ull ap0, ap1;
            SPLAT2(ap0, a0);
            SPLAT2(ap1, a1);
            const ull b0 = *reinterpret_cast<const ull*>(&Bs[p][kk][2 * lane]);
            const ull b1 = *reinterpret_cast<const ull*>(&Bs[p][kk][2 * lane + 64]);
            FMA2(acc[0][0], ap0, b0);
            FMA2(acc[0][1], ap0, b1);
            FMA2(acc[1][0], ap1, b0);
            FMA2(acc[1][1], ap1, b1);
        }

        // stage tile t+1 into the other buffer (safe: different buffer)
        if (t < NT - 1) {
            const int q = 1 - p;
            As[q][ar][ak2 + 0] = aReg.x * ascale;
            As[q][ar][ak2 + 1] = aReg.y * ascale;
            #pragma unroll
            for (int e = 0; e < 2; e++) {
                int idx = tid + e * 512;
                int c = idx >> 3, k4 = (idx & 7) * 4;
                Bs[q][k4 + 0][c] = bReg[e].x;
                Bs[q][k4 + 1][c] = bReg[e].y;
                Bs[q][k4 + 2][c] = bReg[e].z;
                Bs[q][k4 + 3][c] = bReg[e].w;
            }
        }
    }

    // Epilogue: per row i: S = sum_c C[i,c]; neg += sum_c n_c * exp(S - C[i,c])
    double warp_neg = 0.0;
    #pragma unroll
    for (int ii = 0; ii < 2; ii++) {
        float c00, c01, c10, c11;
        asm("mov.b64 {%0, %1}, %2;" : "=f"(c00), "=f"(c01) : "l"(acc[ii][0]));
        asm("mov.b64 {%0, %1}, %2;" : "=f"(c10), "=f"(c11) : "l"(acc[ii][1]));
        float s = c00 + c01 + c10 + c11;
        #pragma unroll
        for (int off = 16; off > 0; off >>= 1)
            s += __shfl_xor_sync(0xffffffffu, s, off);   // S_i allreduce
        float pterm = n0 * expf(s - c00) + n1 * expf(s - c01)
                    + n2 * expf(s - c10) + n3 * expf(s - c11);
        #pragma unroll
        for (int off = 16; off > 0; off >>= 1)
            pterm += __shfl_xor_sync(0xffffffffu, pterm, off);
        warp_neg += (double)pterm;
    }
    if (lane == 0) bneg[warp] = warp_neg;
    __syncthreads();

    if (tid == 0) {
        double bsum = 0.0;
        #pragma unroll
        for (int w = 0; w < 16; w++) bsum += bneg[w];
        atomicAdd(&g_neg, bsum);
        __threadfence();
        unsigned t = atomicAdd(&g_fin, 1u);
        if (t == NBLK - 1) {
            // loss = N*log(neg) + sumexp/neg - sumd
            // (sum_i log1p(exp(d_i)/neg) == sumexp/neg to ~1e-10 abs since
            //  neg >= ~1e5 and exp(d_i) <= e; verified rel_err 9.3e-8)
            const double neg  = atomicAdd(&g_neg, 0.0);
            const double sd   = atomicAdd(&g_sumd, 0.0);
            const double sexp = atomicAdd(&g_sumexpd, 0.0);
            out[0] = (float)((double)N * log(neg) + sexp / neg - sd);
        }
    }
}

// ---------------------------------------------------------------------------
extern "C" void kernel_launch(void* const* d_in, const int* in_sizes, int n_in,
                              void* d_out, int out_size) {
    const float* img    = (const float*)d_in[0];
    const float* txt    = (const float*)d_in[1];
    const int*   labels = (const int*)d_in[2];
    float* out = (float*)d_out;

    zero_kernel<<<(NC * D + 255) / 256, 256>>>();
    rownorm_kernel<<<N, 128>>>(img, txt, labels);
    gemm_neg_kernel<<<NBLK, 512>>>(txt, out);
}

// round 6
// speedup vs baseline: 1.0398x; 1.0398x over previous
#include <cuda_runtime.h>
#include <cuda_bf16.h>

// Problem constants
#define N 4096
#define D 512
#define NC 100          // real classes
#define NCP 128         // padded classes
#define ROWS_B 32       // rows per GEMM block
#define KT 32           // k-tile
#define NBLK (N / ROWS_B)   // 128 compute blocks

typedef unsigned long long ull;

// Packed fp32x2 FMA (Blackwell)
#define FMA2(d, a, b) \
    asm("fma.rn.f32x2 %0, %1, %2, %3;" : "=l"(d) : "l"(a), "l"(b), "l"(d))

__device__ __forceinline__ ull splat2(float f) {
    ull r;
    asm("mov.b64 %0, {%1, %1};" : "=l"(r) : "f"(f));
    return r;
}

// Scratch (device globals; no allocation anywhere)
__device__ __align__(16) float g_txt_n[N * D];   // normalized text features
__device__ float  g_d[N];                         // per-row <img_n, txt_n>
__device__ __align__(16) float g_G[NC * D];       // class sums of img_n, [c][d]
__device__ int    g_cnt[NCP];                     // class counts
__device__ double g_neg;                          // neg accumulator
__device__ double g_sumd;                         // sum_i d_i
__device__ double g_sumexpd;                      // sum_i exp(d_i)
__device__ unsigned int g_fin;                    // epilogue ticket

// ---------------------------------------------------------------------------
// Kernel 0: zero scratch accumulators (runs every replay)
// ---------------------------------------------------------------------------
__global__ void zero_kernel() {
    int idx = blockIdx.x * blockDim.x + threadIdx.x;
    if (idx < NC * D) g_G[idx] = 0.0f;
    if (idx < NCP)    g_cnt[idx] = 0;
    if (idx == 0) { g_neg = 0.0; g_sumd = 0.0; g_sumexpd = 0.0; g_fin = 0u; }
}

// ---------------------------------------------------------------------------
// Kernel 1 (R3-proven): normalize, store txt_n + d_i, scatter img_n into G.
// grid = N blocks, 128 threads (thread owns 4 consecutive dims, float4)
// ---------------------------------------------------------------------------
__global__ void __launch_bounds__(128) rownorm_kernel(
    const float* __restrict__ img,
    const float* __restrict__ txt,
    const int* __restrict__ labels)
{
    const int i    = blockIdx.x;
    const int tid  = threadIdx.x;
    const int lane = tid & 31;
    const int warp = tid >> 5;

    const float4 a = reinterpret_cast<const float4*>(img + (size_t)i * D)[tid];
    const float4 b = reinterpret_cast<const float4*>(txt + (size_t)i * D)[tid];

    float sii = a.x*a.x + a.y*a.y + a.z*a.z + a.w*a.w;
    float stt = b.x*b.x + b.y*b.y + b.z*b.z + b.w*b.w;
    float sit = a.x*b.x + a.y*b.y + a.z*b.z + a.w*b.w;

    #pragma unroll
    for (int off = 16; off > 0; off >>= 1) {
        sii += __shfl_xor_sync(0xffffffffu, sii, off);
        stt += __shfl_xor_sync(0xffffffffu, stt, off);
        sit += __shfl_xor_sync(0xffffffffu, sit, off);
    }
    __shared__ float red[3][4];
    if (lane == 0) { red[0][warp] = sii; red[1][warp] = stt; red[2][warp] = sit; }
    __syncthreads();
    sii = red[0][0] + red[0][1] + red[0][2] + red[0][3];
    stt = red[1][0] + red[1][1] + red[1][2] + red[1][3];
    sit = red[2][0] + red[2][1] + red[2][2] + red[2][3];

    const float rimg = rsqrtf(sii);
    const float rtxt = rsqrtf(stt);
    int c = labels[i];
    c = min(max(c, 0), NC - 1);

    float4 tn;
    tn.x = b.x * rtxt; tn.y = b.y * rtxt; tn.z = b.z * rtxt; tn.w = b.w * rtxt;
    reinterpret_cast<float4*>(g_txt_n + (size_t)i * D)[tid] = tn;

    float* gc = g_G + (size_t)c * D + tid * 4;
    atomicAdd(gc + 0, a.x * rimg);
    atomicAdd(gc + 1, a.y * rimg);
    atomicAdd(gc + 2, a.z * rimg);
    atomicAdd(gc + 3, a.w * rimg);

    if (tid == 0) {
        g_d[i] = sit * rimg * rtxt;   // plain store (no hot atomics)
        atomicAdd(&g_cnt[c], 1);
    }
}

// ---------------------------------------------------------------------------
// Kernel 2: C = txt_n @ G^T fused with neg reduction; last block writes loss.
// grid = 128 blocks, 256 threads (8 warps).
// Warp w owns rows 4w..4w+3; lane L owns class pairs (2L,2L+1),(2L+64,2L+65).
// A stored pre-splatted ({a,a} ull) -> k-pair LDS.128; B read as LDS.64.
// Per warp-kk-pair: 4 LDS.128 + 4 LDS.64 + 16 FMA2  (0.5 LDS/FMA2).
// ---------------------------------------------------------------------------
__global__ void __launch_bounds__(256) gemm_neg_kernel(float* __restrict__ out)
{
    __shared__ __align__(16) ull As[ROWS_B][KT + 2];  // [row][kk] = {a,a}, stride 34
    __shared__ float Bs[KT][NCP + 2];                 // [k][class], stride 130
    __shared__ double bred[8][3];                     // per-warp {neg, sumd, sumexp}

    const int tid  = threadIdx.x;
    const int lane = tid & 31;
    const int warp = tid >> 5;
    const int row0 = blockIdx.x * ROWS_B;

    // class counts for this lane's 4 classes (padded -> 0)
    const float n0 = (float)g_cnt[2*lane];
    const float n1 = (float)g_cnt[2*lane + 1];
    const float n2 = (float)g_cnt[2*lane + 64];
    const float n3 = (float)g_cnt[2*lane + 65];

    ull acc[4][2] = {};

    // staging addressing (constant per thread)
    const int ar  = tid >> 3;            // row 0..31
    const int ak4 = (tid & 7) * 4;       // k offset 0..28
    const float4 zero4 = make_float4(0.f, 0.f, 0.f, 0.f);

    float4 aReg;
    float4 bReg[4];

    // prefetch tile 0
    aReg = *reinterpret_cast<const float4*>(&g_txt_n[(size_t)(row0 + ar) * D + ak4]);
    #pragma unroll
    for (int e = 0; e < 4; e++) {
        int idx = tid + e * 256;
        int c = idx >> 3, k4 = (idx & 7) * 4;
        bReg[e] = (c < NC)
            ? *reinterpret_cast<const float4*>(&g_G[(size_t)c * D + k4])
            : zero4;
    }

    for (int t = 0; t < D / KT; t++) {
        // commit prefetched tile to smem (A pre-splatted, STS.128 x2)
        {
            ulonglong2 s0, s1;
            s0.x = splat2(aReg.x); s0.y = splat2(aReg.y);
            s1.x = splat2(aReg.z); s1.y = splat2(aReg.w);
            *reinterpret_cast<ulonglong2*>(&As[ar][ak4])     = s0;
            *reinterpret_cast<ulonglong2*>(&As[ar][ak4 + 2]) = s1;
        }
        #pragma unroll
        for (int e = 0; e < 4; e++) {
            int idx = tid + e * 256;
            int c = idx >> 3, k4 = (idx & 7) * 4;
            Bs[k4 + 0][c] = bReg[e].x;
            Bs[k4 + 1][c] = bReg[e].y;
            Bs[k4 + 2][c] = bReg[e].z;
            Bs[k4 + 3][c] = bReg[e].w;
        }
        __syncthreads();

        // prefetch next tile (overlaps compute)
        if (t < D / KT - 1) {
            const int k0 = (t + 1) * KT;
            aReg = *reinterpret_cast<const float4*>(&g_txt_n[(size_t)(row0 + ar) * D + k0 + ak4]);
            #pragma unroll
            for (int e = 0; e < 4; e++) {
                int idx = tid + e * 256;
                int c = idx >> 3, k4 = (idx & 7) * 4;
                bReg[e] = (c < NC)
                    ? *reinterpret_cast<const float4*>(&g_G[(size_t)c * D + k0 + k4])
                    : zero4;
            }
        }

        // compute: k-pairs, 8 LDS + 16 FMA2 per warp-pair
        #pragma unroll
        for (int kk = 0; kk < KT; kk += 2) {
            const ull b00 = *reinterpret_cast<const ull*>(&Bs[kk][2 * lane]);
            const ull b01 = *reinterpret_cast<const ull*>(&Bs[kk][2 * lane + 64]);
            const ull b10 = *reinterpret_cast<const ull*>(&Bs[kk + 1][2 * lane]);
            const ull b11 = *reinterpret_cast<const ull*>(&Bs[kk + 1][2 * lane + 64]);
            #pragma unroll
            for (int ii = 0; ii < 4; ii++) {
                const ulonglong2 av =
                    *reinterpret_cast<const ulonglong2*>(&As[warp * 4 + ii][kk]);
                FMA2(acc[ii][0], av.x, b00);
                FMA2(acc[ii][1], av.x, b01);
                FMA2(acc[ii][0], av.y, b10);
                FMA2(acc[ii][1], av.y, b11);
            }
        }
        __syncthreads();
    }

    // Epilogue: per row i: S = sum_c C[i,c]; neg_i = sum_c n_c * exp(S - C[i,c])
    double warp_neg = 0.0;
    #pragma unroll
    for (int ii = 0; ii < 4; ii++) {
        float c00, c01, c10, c11;
        asm("mov.b64 {%0, %1}, %2;" : "=f"(c00), "=f"(c01) : "l"(acc[ii][0]));
        asm("mov.b64 {%0, %1}, %2;" : "=f"(c10), "=f"(c11) : "l"(acc[ii][1]));
        float s = c00 + c01 + c10 + c11;
        #pragma unroll
        for (int off = 16; off > 0; off >>= 1)
            s += __shfl_xor_sync(0xffffffffu, s, off);   // S_i allreduce
        float p = n0 * expf(s - c00) + n1 * expf(s - c01)
                + n2 * expf(s - c10) + n3 * expf(s - c11);
        #pragma unroll
        for (int off = 16; off > 0; off >>= 1)
            p += __shfl_xor_sync(0xffffffffu, p, off);
        warp_neg += (double)p;
    }

    // warp 0 also reduces this block's d_i contribution (plain loads, no hot atomics)
    double warp_sd = 0.0, warp_se = 0.0;
    if (warp == 0) {
        const float dv = g_d[row0 + lane];
        double sd = (double)dv;
        double se = (double)expf(dv);
        #pragma unroll
        for (int off = 16; off > 0; off >>= 1) {
            sd += __shfl_xor_sync(0xffffffffu, sd, off);
            se += __shfl_xor_sync(0xffffffffu, se, off);
        }
        warp_sd = sd; warp_se = se;
    }

    if (lane == 0) { bred[warp][0] = warp_neg; bred[warp][1] = warp_sd; bred[warp][2] = warp_se; }
    __syncthreads();

    if (tid == 0) {
        double bneg = 0.0;
        #pragma unroll
        for (int w = 0; w < 8; w++) bneg += bred[w][0];
        atomicAdd(&g_neg, bneg);
        atomicAdd(&g_sumd, bred[0][1]);
        atomicAdd(&g_sumexpd, bred[0][2]);
        __threadfence();
        unsigned t = atomicAdd(&g_fin, 1u);
        if (t == NBLK - 1) {
            // loss = N*log(neg) + sumexp/neg - sumd
            // (sum_i log1p(exp(d_i)/neg) == sumexp/neg to ~1e-10 abs since
            //  neg >= ~1e5 and exp(d_i) <= e; validated at rel_err 9.3e-8)
            const double neg  = atomicAdd(&g_neg, 0.0);
            const double sd   = atomicAdd(&g_sumd, 0.0);
            const double sexp = atomicAdd(&g_sumexpd, 0.0);
            out[0] = (float)((double)N * log(neg) + sexp / neg - sd);
        }
    }
}

// ---------------------------------------------------------------------------
extern "C" void kernel_launch(void* const* d_in, const int* in_sizes, int n_in,
                              void* d_out, int out_size) {
    const float* img    = (const float*)d_in[0];
    const float* txt    = (const float*)d_in[1];
    const int*   labels = (const int*)d_in[2];
    float* out = (float*)d_out;

    zero_kernel<<<(NC * D + 255) / 256, 256>>>();
    rownorm_kernel<<<N, 128>>>(img, txt, labels);
    gemm_neg_kernel<<<NBLK, 256>>>(out);
}

// round 7
// speedup vs baseline: 1.0457x; 1.0056x over previous
#include <cuda_runtime.h>
#include <cuda_bf16.h>

#define N 4096
#define D 512
#define NC 100
#define NCP 128
#define NBLK 128
#define TPB 256

typedef unsigned long long ull;

#define FMA2(d_, a_, b_) \
    asm("fma.rn.f32x2 %0, %1, %2, %3;" : "=l"(d_) : "l"(a_), "l"(b_), "l"(d_))

__device__ __forceinline__ ull splat2(float f) {
    ull r; asm("mov.b64 %0, {%1, %1};" : "=l"(r) : "f"(f)); return r;
}
__device__ __forceinline__ void unpack2(ull v, float& lo, float& hi) {
    asm("mov.b64 {%0, %1}, %2;" : "=f"(lo), "=f"(hi) : "l"(v));
}

// Device scratch (load-time zeroed; self-cleaning across graph replays)
__device__ float g_G[NC * D];                       // [c][k] REDG target (zeroed phase 0)
__device__ __align__(16) float g_GT[D * NCP];       // [k][c]; cols >= NC stay 0 forever
__device__ int g_cnt[NCP];
__device__ double g_neg, g_sumd, g_sumexpd;
__device__ unsigned g_fin;
__device__ unsigned g_barA[4], g_barD[4];

// Software grid barrier: arrive/depart counters, self-resetting.
// Safe: all NBLK blocks are co-resident (128 <= 148 SMs, 1 block/SM).
__device__ __forceinline__ void gridbar(int id) {
    __syncthreads();
    if (threadIdx.x == 0) {
        __threadfence();
        atomicAdd(&g_barA[id], 1u);
        while (*(volatile unsigned*)&g_barA[id] < (unsigned)NBLK) __nanosleep(32);
        unsigned dd = atomicAdd(&g_barD[id], 1u);
        if (dd == (unsigned)(NBLK - 1)) { g_barD[id] = 0u; g_barA[id] = 0u; __threadfence(); }
    }
    __syncthreads();
}

__device__ __forceinline__ float shfl_sum(float v) {
    #pragma unroll
    for (int off = 16; off > 0; off >>= 1)
        v += __shfl_xor_sync(0xffffffffu, v, off);
    return v;
}

__global__ void __launch_bounds__(TPB, 1) fused_kernel(
    const float* __restrict__ img,
    const float* __restrict__ txt,
    const int*   __restrict__ labels,
    float* __restrict__ out)
{
    extern __shared__ float smem[];
    // layout: txt4 [8 quads][512] float4 = 16384 floats (64KB)
    //         sd_sm[32], Shalf[32][2], bred region (doubles)
    float*  txt4f = smem;                       // as float4*: quad*512 + k
    float*  sd_sm = smem + 16384;               // 32
    float*  Shalf = sd_sm + 32;                 // 64
    double* bredd = (double*)(Shalf + 64);      // 8 warp-neg + 2 (sd,se) ; offset 16480*4 = 65920, 8B aligned

    const int tid  = threadIdx.x;
    const int lane = tid & 31;
    const int w    = tid >> 5;         // warp 0..7
    const int b    = blockIdx.x;
    const int row0 = b * 32;

    // ---------------- phase 0: zero accumulator state ----------------
    {
        const float4 z4 = make_float4(0.f, 0.f, 0.f, 0.f);
        if (tid < 100) reinterpret_cast<float4*>(g_G)[b * 100 + tid] = z4;  // 12800 float4 total
        if (b == 0) {
            if (tid < NCP) g_cnt[tid] = 0;
            if (tid == 0) { g_neg = 0.0; g_sumd = 0.0; g_sumexpd = 0.0; }
        }
    }
    gridbar(0);

    // ---------------- phase 1: warp w owns rows row0+4w .. +3 ----------------
    // k assignment per lane: k = j*32 + lane (coalesced LDG.32 / REDG.32)
    float tkeep[4][16];
    #pragma unroll 1
    for (int r4 = 0; r4 < 4; r4++) {
        const int r = row0 + w * 4 + r4;
        const float* ip = img + (size_t)r * D;
        const float* tp = txt + (size_t)r * D;
        float av[16], bv[16];
        #pragma unroll
        for (int j = 0; j < 16; j++) { av[j] = ip[j * 32 + lane]; bv[j] = tp[j * 32 + lane]; }

        float sii = 0.f, stt = 0.f, sit = 0.f;
        #pragma unroll
        for (int j = 0; j < 16; j++) {
            sii = fmaf(av[j], av[j], sii);
            stt = fmaf(bv[j], bv[j], stt);
            sit = fmaf(av[j], bv[j], sit);
        }
        sii = shfl_sum(sii); stt = shfl_sum(stt); sit = shfl_sum(sit);

        const float rimg = rsqrtf(sii);
        const float rtxt = rsqrtf(stt);
        int c = labels[r];
        c = min(max(c, 0), NC - 1);

        // coalesced scalar REDG scatter of normalized image row
        float* gc = g_G + (size_t)c * D;
        #pragma unroll
        for (int j = 0; j < 16; j++)
            atomicAdd(gc + j * 32 + lane, av[j] * rimg);

        #pragma unroll
        for (int j = 0; j < 16; j++) tkeep[r4][j] = bv[j] * rtxt;

        if (lane == 0) {
            sd_sm[w * 4 + r4] = sit * rimg * rtxt;
            atomicAdd(&g_cnt[c], 1);
        }
    }
    // write txt4 quad w: float4 {rows 4w..4w+3} at k = j*32+lane  (STS.128, conflict-free)
    #pragma unroll
    for (int j = 0; j < 16; j++) {
        float4 v = make_float4(tkeep[0][j], tkeep[1][j], tkeep[2][j], tkeep[3][j]);
        reinterpret_cast<float4*>(txt4f)[w * 512 + j * 32 + lane] = v;
    }

    gridbar(1);   // G + cnt complete chip-wide

    // ---------------- transpose G[c][k] -> G_T[k][c] ----------------
    {
        const int f = b * TPB + tid;      // 12800 float4s of G
        if (f < (NC * D) / 4) {
            const int c  = f >> 7;        // f / 128 (128 float4 per class row)
            const int kq = f & 127;
            float4 v = reinterpret_cast<const float4*>(g_G)[f];
            g_GT[(kq * 4 + 0) * NCP + c] = v.x;
            g_GT[(kq * 4 + 1) * NCP + c] = v.y;
            g_GT[(kq * 4 + 2) * NCP + c] = v.z;
            g_GT[(kq * 4 + 3) * NCP + c] = v.w;
        }
    }
    gridbar(2);   // G_T ready

    // ---------------- phase 2: GEMM + neg ----------------
    // warp = (g = w>>1 row-group of 8 rows, h = w&1 class-half of 64)
    // lane owns classes c0 = 64h + 2*lane, c0+1
    const int g  = w >> 1;
    const int h  = w & 1;
    const int c0 = h * 64 + 2 * lane;
    const float n0 = (float)g_cnt[c0];
    const float n1 = (float)g_cnt[c0 + 1];

    ull acc[2][2][2] = {};   // [quad q][row-pair rp][class e]
    const float4* A0 = reinterpret_cast<const float4*>(txt4f) + (2 * g) * 512;
    const float4* A1 = A0 + 512;
    const float*  BT = g_GT + c0;

    #pragma unroll 8
    for (int k = 0; k < D; k++) {
        const float2 bb = __ldg(reinterpret_cast<const float2*>(BT + (size_t)k * NCP));
        const ull s0 = splat2(bb.x);
        const ull s1 = splat2(bb.y);
        const float4 a0 = A0[k];
        const float4 a1 = A1[k];
        const ulonglong2 u0 = *reinterpret_cast<const ulonglong2*>(&a0);
        const ulonglong2 u1 = *reinterpret_cast<const ulonglong2*>(&a1);
        FMA2(acc[0][0][0], u0.x, s0); FMA2(acc[0][0][1], u0.x, s1);
        FMA2(acc[0][1][0], u0.y, s0); FMA2(acc[0][1][1], u0.y, s1);
        FMA2(acc[1][0][0], u1.x, s0); FMA2(acc[1][0][1], u1.x, s1);
        FMA2(acc[1][1][0], u1.y, s0); FMA2(acc[1][1][1], u1.y, s1);
    }

    // epilogue pass 1: per-row half-sums S_h (this warp's 64 classes)
    #pragma unroll
    for (int q = 0; q < 2; q++)
        #pragma unroll
        for (int rp = 0; rp < 2; rp++) {
            float C0a, C0b, C1a, C1b;
            unpack2(acc[q][rp][0], C0a, C0b);   // rows e0, e1 of class c0
            unpack2(acc[q][rp][1], C1a, C1b);   // rows e0, e1 of class c0+1
            float sp0 = shfl_sum(C0a + C1a);
            float sp1 = shfl_sum(C0b + C1b);
            if (lane == 0) {
                const int rl = 8 * g + 4 * q + 2 * rp;
                Shalf[(rl + 0) * 2 + h] = sp0;
                Shalf[(rl + 1) * 2 + h] = sp1;
            }
        }
    __syncthreads();

    // epilogue pass 2: neg contributions with full S
    float pacc = 0.f;
    #pragma unroll
    for (int q = 0; q < 2; q++)
        #pragma unroll
        for (int rp = 0; rp < 2; rp++) {
            float C0a, C0b, C1a, C1b;
            unpack2(acc[q][rp][0], C0a, C0b);
            unpack2(acc[q][rp][1], C1a, C1b);
            const int rl = 8 * g + 4 * q + 2 * rp;
            const float S0 = Shalf[(rl + 0) * 2 + 0] + Shalf[(rl + 0) * 2 + 1];
            const float S1 = Shalf[(rl + 1) * 2 + 0] + Shalf[(rl + 1) * 2 + 1];
            pacc += n0 * expf(S0 - C0a) + n1 * expf(S0 - C1a);
            pacc += n0 * expf(S1 - C0b) + n1 * expf(S1 - C1b);
        }
    pacc = shfl_sum(pacc);
    if (lane == 0) bredd[w] = (double)pacc;

    // warp 0: block's sumd / sumexpd from sd_sm
    if (w == 0) {
        const float dv = sd_sm[lane];
        float se = expf(dv);
        float sd = shfl_sum(dv);
        se = shfl_sum(se);
        if (lane == 0) { bredd[8] = (double)sd; bredd[9] = (double)se; }
    }
    __syncthreads();

    if (tid == 0) {
        double bneg = 0.0;
        #pragma unroll
        for (int ww = 0; ww < 8; ww++) bneg += bredd[ww];
        atomicAdd(&g_neg, bneg);
        atomicAdd(&g_sumd, bredd[8]);
        atomicAdd(&g_sumexpd, bredd[9]);
        __threadfence();
        unsigned t = atomicAdd(&g_fin, 1u);
        if (t == (unsigned)(NBLK - 1)) {
            // loss = N*log(neg) + sumexp/neg - sumd   (validated, rel_err 9.3e-8)
            const double neg  = atomicAdd(&g_neg, 0.0);
            const double sd   = atomicAdd(&g_sumd, 0.0);
            const double sexp = atomicAdd(&g_sumexpd, 0.0);
            out[0] = (float)((double)N * log(neg) + sexp / neg - sd);
            g_fin = 0u;          // self-clean for next replay
            __threadfence();
        }
    }
}

// ---------------------------------------------------------------------------
extern "C" void kernel_launch(void* const* d_in, const int* in_sizes, int n_in,
                              void* d_out, int out_size) {
    const float* img    = (const float*)d_in[0];
    const float* txt    = (const float*)d_in[1];
    const int*   labels = (const int*)d_in[2];
    float* out = (float*)d_out;

    const int smem_bytes = (16384 + 32 + 64) * 4 + 16 * 8;  // txt4 + sd + Shalf + bred
    cudaFuncSetAttribute(fused_kernel, cudaFuncAttributeMaxDynamicSharedMemorySize, smem_bytes);
    fused_kernel<<<NBLK, TPB, smem_bytes>>>(img, txt, labels, out);
}

// round 8
// speedup vs baseline: 1.4321x; 1.3696x over previous
#include <cuda_runtime.h>
#include <cuda_bf16.h>

// Problem constants
#define N 4096
#define D 512
#define NC 100          // real classes
#define NCP 128         // padded classes
#define ROWS_B 32       // rows per GEMM block
#define KT 32           // k-tile
#define NBLK (N / ROWS_B)   // 128 gemm blocks

// Packed fp32x2 FMA (Blackwell): d = a*b + d elementwise on 2 floats
#define FMA2(d, a, b) \
    asm("fma.rn.f32x2 %0, %1, %2, %3;" : "=l"(d) : "l"(a), "l"(b), "l"(d))
#define SPLAT2(d, f) \
    asm("mov.b64 %0, {%1, %1};" : "=l"(d) : "f"(f))

// Scratch (device globals; no allocation in kernel_launch)
__device__ __align__(16) float g_txt_n[N * D];   // normalized text features
__device__ float g_d[N];                          // per-row <img_n, txt_n>
__device__ __align__(16) float g_G[NC * D];       // class sums of img_n, [c][d]
__device__ int    g_cnt[NCP];                     // class counts
__device__ double g_neg;                          // neg accumulator
__device__ double g_sumd;                         // sum_i d_i
__device__ double g_sumexpd;                      // sum_i exp(d_i)
__device__ unsigned int g_fin;                    // epilogue ticket

// ---------------------------------------------------------------------------
// Kernel 0: zero scratch accumulators (runs every replay)
// ---------------------------------------------------------------------------
__global__ void zero_kernel() {
    const int idx = blockIdx.x * blockDim.x + threadIdx.x;
    const float4 z4 = make_float4(0.f, 0.f, 0.f, 0.f);
    if (idx < (NC * D) / 4) reinterpret_cast<float4*>(g_G)[idx] = z4;
    if (idx < NCP)          g_cnt[idx] = 0;
    if (idx == 0) { g_neg = 0.0; g_sumd = 0.0; g_sumexpd = 0.0; g_fin = 0u; }
}

// ---------------------------------------------------------------------------
// Kernel 1 (R3-proven): normalize, store txt_n + d_i, scatter img_n into G.
// grid = N blocks, 128 threads (thread owns 4 consecutive dims, float4).
// Delta vs R3: single red.global.add.v4.f32 instead of 4 scalar atomicAdds.
// ---------------------------------------------------------------------------
__global__ void __launch_bounds__(128) rownorm_kernel(
    const float* __restrict__ img,
    const float* __restrict__ txt,
    const int* __restrict__ labels)
{
    const int i    = blockIdx.x;
    const int tid  = threadIdx.x;
    const int lane = tid & 31;
    const int warp = tid >> 5;

    const float4 a = reinterpret_cast<const float4*>(img + (size_t)i * D)[tid];
    const float4 b = reinterpret_cast<const float4*>(txt + (size_t)i * D)[tid];

    float sii = a.x*a.x + a.y*a.y + a.z*a.z + a.w*a.w;
    float stt = b.x*b.x + b.y*b.y + b.z*b.z + b.w*b.w;
    float sit = a.x*b.x + a.y*b.y + a.z*b.z + a.w*b.w;

    #pragma unroll
    for (int off = 16; off > 0; off >>= 1) {
        sii += __shfl_xor_sync(0xffffffffu, sii, off);
        stt += __shfl_xor_sync(0xffffffffu, stt, off);
        sit += __shfl_xor_sync(0xffffffffu, sit, off);
    }
    __shared__ float red[3][4];
    if (lane == 0) { red[0][warp] = sii; red[1][warp] = stt; red[2][warp] = sit; }
    __syncthreads();
    sii = red[0][0] + red[0][1] + red[0][2] + red[0][3];
    stt = red[1][0] + red[1][1] + red[1][2] + red[1][3];
    sit = red[2][0] + red[2][1] + red[2][2] + red[2][3];

    const float rimg = rsqrtf(sii);
    const float rtxt = rsqrtf(stt);
    int c = labels[i];
    c = min(max(c, 0), NC - 1);

    // store normalized text row
    float4 tn;
    tn.x = b.x * rtxt; tn.y = b.y * rtxt; tn.z = b.z * rtxt; tn.w = b.w * rtxt;
    reinterpret_cast<float4*>(g_txt_n + (size_t)i * D)[tid] = tn;

    // scatter normalized image row into G[c][:] with ONE vector reduction
    // (16B-aligned: g_G is align(16) and offset is tid*16 bytes)
    float* gc = g_G + (size_t)c * D + tid * 4;
    asm volatile("red.global.add.v4.f32 [%0], {%1, %2, %3, %4};"
                 :: "l"(gc), "f"(a.x * rimg), "f"(a.y * rimg),
                    "f"(a.z * rimg), "f"(a.w * rimg)
                 : "memory");

    if (tid == 0) {
        g_d[i] = sit * rimg * rtxt;
        atomicAdd(&g_cnt[c], 1);
    }
}

// ---------------------------------------------------------------------------
// Kernel 2 (R3-proven gemm, verbatim inner loop) + folded finish.
// grid = 128 blocks, 256 threads.
// Warp w owns rows 4w..4w+3; lane L owns class pairs (2L,2L+1),(2L+64,2L+65).
// ---------------------------------------------------------------------------
__global__ void __launch_bounds__(256) gemm_neg_kernel(float* __restrict__ out)
{
    __shared__ float As[ROWS_B][KT + 1];   // [row][k], broadcast reads
    __shared__ float Bs[KT][NCP + 2];      // [k][class], stride 130
    __shared__ double bred[8][3];          // per-warp {neg, sumd, sumexp}

    const int tid  = threadIdx.x;
    const int lane = tid & 31;
    const int warp = tid >> 5;
    const int row0 = blockIdx.x * ROWS_B;

    // class counts for this lane's 4 classes (padded -> 0)
    const float n0 = (float)g_cnt[2*lane];
    const float n1 = (float)g_cnt[2*lane + 1];
    const float n2 = (float)g_cnt[2*lane + 64];
    const float n3 = (float)g_cnt[2*lane + 65];

    unsigned long long accp[4][2] = {};

    const int ar  = tid >> 3;            // A row 0..31
    const int ak4 = (tid & 7) * 4;       // A k offset 0..28
    const float4 zero4 = make_float4(0.f, 0.f, 0.f, 0.f);

    float4 aReg;
    float4 bReg[4];

    // prefetch tile 0
    aReg = *reinterpret_cast<const float4*>(&g_txt_n[(size_t)(row0 + ar) * D + ak4]);
    #pragma unroll
    for (int e = 0; e < 4; e++) {
        int idx = tid + e * 256;
        int c = idx >> 3, k4 = (idx & 7) * 4;
        bReg[e] = (c < NC)
            ? *reinterpret_cast<const float4*>(&g_G[(size_t)c * D + k4])
            : zero4;
    }

    for (int t = 0; t < D / KT; t++) {
        As[ar][ak4 + 0] = aReg.x;
        As[ar][ak4 + 1] = aReg.y;
        As[ar][ak4 + 2] = aReg.z;
        As[ar][ak4 + 3] = aReg.w;
        #pragma unroll
        for (int e = 0; e < 4; e++) {
            int idx = tid + e * 256;
            int c = idx >> 3, k4 = (idx & 7) * 4;
            Bs[k4 + 0][c] = bReg[e].x;
            Bs[k4 + 1][c] = bReg[e].y;
            Bs[k4 + 2][c] = bReg[e].z;
            Bs[k4 + 3][c] = bReg[e].w;
        }
        __syncthreads();

        if (t < D / KT - 1) {
            int k0 = (t + 1) * KT;
            aReg = *reinterpret_cast<const float4*>(&g_txt_n[(size_t)(row0 + ar) * D + k0 + ak4]);
            #pragma unroll
            for (int e = 0; e < 4; e++) {
                int idx = tid + e * 256;
                int c = idx >> 3, k4 = (idx & 7) * 4;
                bReg[e] = (c < NC)
                    ? *reinterpret_cast<const float4*>(&g_G[(size_t)c * D + k0 + k4])
                    : zero4;
            }
        }

        #pragma unroll
        for (int kk = 0; kk < KT; kk++) {
            const unsigned long long b0 =
                *reinterpret_cast<const unsigned long long*>(&Bs[kk][2 * lane]);
            const unsigned long long b1 =
                *reinterpret_cast<const unsigned long long*>(&Bs[kk][2 * lane + 64]);
            #pragma unroll
            for (int ii = 0; ii < 4; ii++) {
                float av = As[warp * 4 + ii][kk];
                unsigned long long ap;
                SPLAT2(ap, av);
                FMA2(accp[ii][0], ap, b0);
                FMA2(accp[ii][1], ap, b1);
            }
        }
        __syncthreads();
    }

    // Epilogue: per row i: S = sum_c C[i,c]; neg_i = sum_c n_c * exp(S - C[i,c])
    double warp_neg = 0.0;
    #pragma unroll
    for (int ii = 0; ii < 4; ii++) {
        float c00, c01, c10, c11;
        asm("mov.b64 {%0, %1}, %2;" : "=f"(c00), "=f"(c01) : "l"(accp[ii][0]));
        asm("mov.b64 {%0, %1}, %2;" : "=f"(c10), "=f"(c11) : "l"(accp[ii][1]));
        float s = c00 + c01 + c10 + c11;
        #pragma unroll
        for (int off = 16; off > 0; off >>= 1)
            s += __shfl_xor_sync(0xffffffffu, s, off);   // S_i allreduce
        float p = n0 * expf(s - c00) + n1 * expf(s - c01)
                + n2 * expf(s - c10) + n3 * expf(s - c11);
        #pragma unroll
        for (int off = 16; off > 0; off >>= 1)
            p += __shfl_xor_sync(0xffffffffu, p, off);
        warp_neg += (double)p;
    }

    // warp 0: this block's sumd / sumexpd from g_d (plain loads, no hot atomics)
    double warp_sd = 0.0, warp_se = 0.0;
    if (warp == 0) {
        const float dv = g_d[row0 + lane];
        double sd = (double)dv;
        double se = (double)expf(dv);
        #pragma unroll
        for (int off = 16; off > 0; off >>= 1) {
            sd += __shfl_xor_sync(0xffffffffu, sd, off);
            se += __shfl_xor_sync(0xffffffffu, se, off);
        }
        warp_sd = sd; warp_se = se;
    }

    if (lane == 0) { bred[warp][0] = warp_neg; bred[warp][1] = warp_sd; bred[warp][2] = warp_se; }
    __syncthreads();

    if (tid == 0) {
        double bneg = 0.0;
        #pragma unroll
        for (int w = 0; w < 8; w++) bneg += bred[w][0];
        atomicAdd(&g_neg, bneg);
        atomicAdd(&g_sumd, bred[0][1]);
        atomicAdd(&g_sumexpd, bred[0][2]);
        __threadfence();
        unsigned t = atomicAdd(&g_fin, 1u);
        if (t == NBLK - 1) {
            // loss = N*log(neg) + sumexp/neg - sumd
            // (sum_i log1p(exp(d_i)/neg) == sumexp/neg to ~1e-10 abs since
            //  neg >= ~1e5 and exp(d_i) <= e; validated at rel_err 9.3e-8)
            const double neg  = atomicAdd(&g_neg, 0.0);
            const double sd   = atomicAdd(&g_sumd, 0.0);
            const double sexp = atomicAdd(&g_sumexpd, 0.0);
            out[0] = (float)((double)N * log(neg) + sexp / neg - sd);
        }
    }
}

// ---------------------------------------------------------------------------
extern "C" void kernel_launch(void* const* d_in, const int* in_sizes, int n_in,
                              void* d_out, int out_size) {
    const float* img    = (const float*)d_in[0];
    const float* txt    = (const float*)d_in[1];
    const int*   labels = (const int*)d_in[2];
    float* out = (float*)d_out;

    zero_kernel<<<((NC * D) / 4 + 255) / 256, 256>>>();
    rownorm_kernel<<<N, 128>>>(img, txt, labels);
    gemm_neg_kernel<<<NBLK, 256>>>(out);
}